// round 8
// baseline (speedup 1.0000x reference)
#include <cuda_runtime.h>
#include <cuda_bf16.h>
#include <cstdint>

// CPLSTM_20959440405049 — constant-folded (proof: h0=0 and the multiplicative
// gate g=(h@a)*(x_t@b) give g=0 ==> f=i=o=sigmoid(0)=0.5, g_t=tanh(0)=0 ==>
// c'=0.5*0+0.5*0=0, h'=0.5*tanh(0)=0; by induction h_t=c_t=0 exactly for all t).
// output = dec_b broadcast over (S*B, V); (c_T, h_T) = zeros. rel_err = 0.0.
//
// Round 8: maximize store contiguity — one CTA writes one fully contiguous
// 128 KB row (32 x 4KB dense bursts within a single 2MB page), instead of
// 4KB bursts strided 32KB (R7: 82% DRAM). dec_b is re-read per store but is
// L1-resident (128KB, shared by all ~8 co-resident CTAs per SM) => zero extra
// DRAM traffic, latency hidden at 85% occupancy. Contiguity series so far:
// interleaved 80.8% -> chunk-8 82.0% -> full-row (this).

__global__ void __launch_bounds__(256)
cplstm_row_kernel(const float4* __restrict__ dec_b4,
                  float4* __restrict__ out4,
                  int V4,            // V/4 float4 columns per row
                  int rows,          // S*B rows
                  int tail_blocks,   // CTAs past `rows` that zero the tail
                  size_t tail_off4,  // float4 offset of state tail
                  size_t tail_n4)    // float4 count of state tail
{
    const int row = blockIdx.x;

    if (row < rows) {
        // Fully contiguous 128 KB row: iteration i writes bytes
        // [i*4KB, i*4KB+4KB) of the row; dec_b4[i] comes from L1 after warmup.
        float4* __restrict__ p = out4 + (size_t)row * V4;
        #pragma unroll 4
        for (int i = threadIdx.x; i < V4; i += 256) {
            __stcs(p + i, __ldg(dec_b4 + i));
        }
    } else {
        // Tail CTAs zero the (c_T, h_T) state outputs (256 KB).
        const int t = row - rows;
        const size_t stride = (size_t)tail_blocks * 256;
        const float4 z = make_float4(0.f, 0.f, 0.f, 0.f);
        for (size_t i = (size_t)t * 256 + threadIdx.x; i < tail_n4; i += stride)
            __stcs(&out4[tail_off4 + i], z);
    }
}

// Defensive generic path (only if V % 4 != 0 or odd sizes — not this problem).
__global__ void cplstm_generic_kernel(const float* __restrict__ dec_b,
                                      float* __restrict__ out,
                                      size_t n_total, size_t n_logits, int V)
{
    size_t i = (size_t)blockIdx.x * blockDim.x + threadIdx.x;
    const size_t stride = (size_t)gridDim.x * blockDim.x;
    for (; i < n_total; i += stride) {
        float s = (i < n_logits) ? dec_b[i % (size_t)V] : 0.f;
        __stcs(&out[i], s);
    }
}

extern "C" void kernel_launch(void* const* d_in, const int* in_sizes, int n_in,
                              void* d_out, int out_size)
{
    // metadata order: inp(S,B) int32, emb(V,D), a(H,4R), b(D,4R), ct(4R,H),
    //                 dec_w(V,H), dec_b(V,)
    const float* dec_b = (const float*)d_in[6];
    float*       out   = (float*)d_out;

    const size_t SB = (size_t)in_sizes[0];   // S*B = 4096 rows
    const int    V  = in_sizes[6];           // 32000
    const size_t n_total = (size_t)out_size;
    size_t n_logits = SB * (size_t)V;
    if (n_logits > n_total) n_logits = n_total;

    const size_t n_tail = n_total - n_logits;

    if ((V & 3) != 0 || (n_logits & 3) != 0 || (n_tail & 3) != 0) {
        cplstm_generic_kernel<<<148 * 8, 256>>>(dec_b, out, n_total, n_logits, V);
        return;
    }

    const int V4   = V >> 2;                 // 8000 float4 per row
    const int rows = (int)SB;                // 4096

    // One CTA per row (fully contiguous 128 KB each) + 64 tail CTAs zeroing
    // the 16384-float4 state tail (1 store per tail thread).
    const int tail_blocks = (n_tail > 0) ? 64 : 0;
    dim3 block(256, 1, 1);
    dim3 grid(rows + tail_blocks, 1, 1);

    cplstm_row_kernel<<<grid, block>>>(
        (const float4*)dec_b, (float4*)out, V4, rows, tail_blocks,
        n_logits >> 2, n_tail >> 2);
}

// round 9
// speedup vs baseline: 1.0529x; 1.0529x over previous
#include <cuda_runtime.h>
#include <cuda_bf16.h>
#include <cstdint>

// CPLSTM_20959440405049 — constant-folded (proof: h0=0 and the multiplicative
// gate g=(h@a)*(x_t@b) give g=0 ==> f=i=o=sigmoid(0)=0.5, g_t=tanh(0)=0 ==>
// c'=0.5*0+0.5*0=0, h'=0.5*tanh(0)=0; by induction h_t=c_t=0 exactly for all t).
// output = dec_b broadcast over (S*B, V); (c_T, h_T) = zeros. rel_err = 0.0.
//
// Round 9: revert to R7's register-resident chunked mapping (R8's per-store
// dec_b load throttled store MLP: 82.0% -> 76.4% DRAM). New axis: 256-bit
// stores (st.global.cs.v8.f32, sm_100+). Halves store instructions and L1tex
// wavefronts (L1 was 73.5%, the nearest secondary ceiling), doubles per-warp
// burst to 1KB/instruction. Steady state: STG.256.cs + IADD, value in regs.

__device__ __forceinline__ void stcs_v8(float* p, const float4& a, const float4& b)
{
    asm volatile(
        "st.global.cs.v8.f32 [%0], {%1,%2,%3,%4,%5,%6,%7,%8};"
        :: "l"(p),
           "f"(a.x), "f"(a.y), "f"(a.z), "f"(a.w),
           "f"(b.x), "f"(b.y), "f"(b.z), "f"(b.w)
        : "memory");
}

__global__ void __launch_bounds__(256)
cplstm_v8_kernel(const float4* __restrict__ dec_b4,
                 float* __restrict__ out,
                 int V8,            // V/8 32-byte columns per row
                 int rows,          // S*B rows
                 int chunk,         // contiguous rows per CTA-y
                 size_t tail_off,   // float offset of state tail
                 size_t tail_n8)    // 32-byte chunks in state tail
{
    const int col8 = blockIdx.x * blockDim.x + threadIdx.x;

    if (col8 < V8) {
        // Value loaded ONCE, register-resident (two float4 = one 32B chunk).
        const float4 v0 = __ldg(dec_b4 + 2 * col8);
        const float4 v1 = __ldg(dec_b4 + 2 * col8 + 1);

        const int r0 = blockIdx.y * chunk;
        int rend = r0 + chunk;
        if (rend > rows) rend = rows;

        const size_t rowf = (size_t)V8 * 8;          // floats per row
        float* p = out + (size_t)r0 * rowf + (size_t)col8 * 8;
        #pragma unroll 4
        for (int r = r0; r < rend; ++r) {
            stcs_v8(p, v0, v1);      // 256-bit streaming store
            p += rowf;               // +32 KB
        }
    } else {
        // Overshoot threads zero the 256 KB (c_T, h_T) tail in parallel.
        const int over = gridDim.x * blockDim.x - V8;
        size_t i = (size_t)(col8 - V8) + (size_t)over * blockIdx.y;
        const size_t stride = (size_t)over * gridDim.y;
        const float4 z = make_float4(0.f, 0.f, 0.f, 0.f);
        for (; i < tail_n8; i += stride)
            stcs_v8(out + tail_off + i * 8, z, z);
    }
}

// Defensive generic path (only for odd sizes — not this problem's shapes).
__global__ void cplstm_generic_kernel(const float* __restrict__ dec_b,
                                      float* __restrict__ out,
                                      size_t n_total, size_t n_logits, int V)
{
    size_t i = (size_t)blockIdx.x * blockDim.x + threadIdx.x;
    const size_t stride = (size_t)gridDim.x * blockDim.x;
    for (; i < n_total; i += stride) {
        float s = (i < n_logits) ? dec_b[i % (size_t)V] : 0.f;
        __stcs(&out[i], s);
    }
}

extern "C" void kernel_launch(void* const* d_in, const int* in_sizes, int n_in,
                              void* d_out, int out_size)
{
    // metadata order: inp(S,B) int32, emb(V,D), a(H,4R), b(D,4R), ct(4R,H),
    //                 dec_w(V,H), dec_b(V,)
    const float* dec_b = (const float*)d_in[6];
    float*       out   = (float*)d_out;

    const size_t SB = (size_t)in_sizes[0];   // S*B = 4096 rows
    const int    V  = in_sizes[6];           // 32000
    const size_t n_total = (size_t)out_size;
    size_t n_logits = SB * (size_t)V;
    if (n_logits > n_total) n_logits = n_total;

    const size_t n_tail = n_total - n_logits;

    // v8 path needs: V % 8 == 0 (32B-aligned row stride & columns),
    // logits offset and tail both 32B-multiples.
    if ((V & 7) != 0 || (n_logits & 7) != 0 || (n_tail & 7) != 0) {
        cplstm_generic_kernel<<<148 * 8, 256>>>(dec_b, out, n_total, n_logits, V);
        return;
    }

    const int V8   = V >> 3;                 // 4000 32B columns per row
    const int rows = (int)SB;                // 4096

    // grid.x = 16 col blocks (4096 slots >= 4000; 96 overshoot threads per
    // row-tile zero the tail). gy = 1024, chunk = 4 -> 16384 CTAs (the proven
    // stream count), 4 independent 256-bit stores per main-path thread.
    dim3 block(256, 1, 1);
    int gy = 1024;
    if (gy > rows) gy = rows;
    const int chunk = (rows + gy - 1) / gy;  // 4
    dim3 grid((V8 + 255) / 256, gy, 1);

    if ((int)grid.x * 256 == V8 && n_tail > 0) grid.x += 1;

    cplstm_v8_kernel<<<grid, block>>>(
        (const float4*)dec_b, out, V8, rows, chunk,
        n_logits, n_tail >> 3);
}

// round 10
// speedup vs baseline: 1.0534x; 1.0004x over previous
#include <cuda_runtime.h>
#include <cuda_bf16.h>
#include <cstdint>

// CPLSTM_20959440405049 — constant-folded (proof: h0=0 and the multiplicative
// gate g=(h@a)*(x_t@b) give g=0 ==> f=i=o=sigmoid(0)=0.5, g_t=tanh(0)=0 ==>
// c'=0.5*0+0.5*0=0, h'=0.5*tanh(0)=0; by induction h_t=c_t=0 exactly for all t).
// output = dec_b broadcast over (S*B, V); (c_T, h_T) = zeros. rel_err = 0.0.
//
// Round 10: four configs (v4 interleaved / v4 chunk-8 / full-row / v8 chunk-4)
// all plateau at 6.45-6.50 TB/s with issue<10% — DRAM-write ceiling. Last
// untested store-path knob: evict policy. Swap .cs (evict-first) for default
// write-back so the 126MB L2 can buffer/batch dirty lines before DRAM drain.
// Everything else identical to the measured-best R9 geometry.

__device__ __forceinline__ void st_v8(float* p, const float4& a, const float4& b)
{
    asm volatile(
        "st.global.v8.f32 [%0], {%1,%2,%3,%4,%5,%6,%7,%8};"
        :: "l"(p),
           "f"(a.x), "f"(a.y), "f"(a.z), "f"(a.w),
           "f"(b.x), "f"(b.y), "f"(b.z), "f"(b.w)
        : "memory");
}

__global__ void __launch_bounds__(256)
cplstm_v8_kernel(const float4* __restrict__ dec_b4,
                 float* __restrict__ out,
                 int V8,            // V/8 32-byte columns per row
                 int rows,          // S*B rows
                 int chunk,         // contiguous rows per CTA-y
                 size_t tail_off,   // float offset of state tail
                 size_t tail_n8)    // 32-byte chunks in state tail
{
    const int col8 = blockIdx.x * blockDim.x + threadIdx.x;

    if (col8 < V8) {
        // Value loaded ONCE, register-resident (two float4 = one 32B chunk).
        const float4 v0 = __ldg(dec_b4 + 2 * col8);
        const float4 v1 = __ldg(dec_b4 + 2 * col8 + 1);

        const int r0 = blockIdx.y * chunk;
        int rend = r0 + chunk;
        if (rend > rows) rend = rows;

        const size_t rowf = (size_t)V8 * 8;          // floats per row
        float* p = out + (size_t)r0 * rowf + (size_t)col8 * 8;
        #pragma unroll 4
        for (int r = r0; r < rend; ++r) {
            st_v8(p, v0, v1);        // 256-bit write-back store
            p += rowf;               // +32 KB
        }
    } else {
        // Overshoot threads zero the 256 KB (c_T, h_T) tail in parallel.
        const int over = gridDim.x * blockDim.x - V8;
        size_t i = (size_t)(col8 - V8) + (size_t)over * blockIdx.y;
        const size_t stride = (size_t)over * gridDim.y;
        const float4 z = make_float4(0.f, 0.f, 0.f, 0.f);
        for (; i < tail_n8; i += stride)
            st_v8(out + tail_off + i * 8, z, z);
    }
}

// Defensive generic path (only for odd sizes — not this problem's shapes).
__global__ void cplstm_generic_kernel(const float* __restrict__ dec_b,
                                      float* __restrict__ out,
                                      size_t n_total, size_t n_logits, int V)
{
    size_t i = (size_t)blockIdx.x * blockDim.x + threadIdx.x;
    const size_t stride = (size_t)gridDim.x * blockDim.x;
    for (; i < n_total; i += stride) {
        float s = (i < n_logits) ? dec_b[i % (size_t)V] : 0.f;
        out[i] = s;
    }
}

extern "C" void kernel_launch(void* const* d_in, const int* in_sizes, int n_in,
                              void* d_out, int out_size)
{
    // metadata order: inp(S,B) int32, emb(V,D), a(H,4R), b(D,4R), ct(4R,H),
    //                 dec_w(V,H), dec_b(V,)
    const float* dec_b = (const float*)d_in[6];
    float*       out   = (float*)d_out;

    const size_t SB = (size_t)in_sizes[0];   // S*B = 4096 rows
    const int    V  = in_sizes[6];           // 32000
    const size_t n_total = (size_t)out_size;
    size_t n_logits = SB * (size_t)V;
    if (n_logits > n_total) n_logits = n_total;

    const size_t n_tail = n_total - n_logits;

    // v8 path needs: V % 8 == 0, logits offset and tail both 32B-multiples.
    if ((V & 7) != 0 || (n_logits & 7) != 0 || (n_tail & 7) != 0) {
        cplstm_generic_kernel<<<148 * 8, 256>>>(dec_b, out, n_total, n_logits, V);
        return;
    }

    const int V8   = V >> 3;                 // 4000 32B columns per row
    const int rows = (int)SB;                // 4096

    // grid.x = 16 col blocks (4096 slots >= 4000; 96 overshoot threads per
    // row-tile zero the tail). gy = 1024, chunk = 4 -> 16384 CTAs (the proven
    // stream count), 4 independent 256-bit stores per main-path thread.
    dim3 block(256, 1, 1);
    int gy = 1024;
    if (gy > rows) gy = rows;
    const int chunk = (rows + gy - 1) / gy;  // 4
    dim3 grid((V8 + 255) / 256, gy, 1);

    if ((int)grid.x * 256 == V8 && n_tail > 0) grid.x += 1;

    cplstm_v8_kernel<<<grid, block>>>(
        (const float4*)dec_b, out, V8, rows, chunk,
        n_logits, n_tail >> 3);
}